// round 2
// baseline (speedup 1.0000x reference)
#include <cuda_runtime.h>

// 3-layer LSTM (IN=5, H=50) + FC(50->1), B=1024, T=512.
// Fused persistent kernel, v2: j-ownership + K-split.
//  - thread (j, ks): accumulates gates {j, j+50, j+100, j+150} over its K/4
//    slice (kq = ks, ks+4, ...) for all 7 batch elems; 2-round shfl.bfly
//    combines the 4 K-partials; the 4 owning threads then apply activations
//    and the c/h update in-registers (c never touches smem).
//  - v vectors double-buffered on t-parity: 3 barriers/step total.
//  - weights in smem, [kq][gate][4k] with kq-stride 808 words (=8 mod 32
//    banks) so warp LDS.128 of w and v are conflict-free.

#define T_STEPS   512
#define IN_DIM    5
#define HID       50
#define NB        7
#define NTHREADS  256
#define GRID      148
#define WSTR      808          // floats per kq block (200 gates * 4 + 8 pad)

// smem offsets (floats)
enum {
    W1_OFF = 0,                // 14 kq * 808
    W2_OFF = 11312,            // 25 kq * 808
    W3_OFF = 31512,
    BS_OFF = 51712,            // 3 * 200 combined biases
    V1_OFF = 52312,            // 2 bufs * 7 * 56
    V2_OFF = 53096,            // 2 bufs * 7 * 100
    V3_OFF = 54496,
    SH_FLOATS = 55896          // 223584 bytes
};
#define V1B 392
#define V2B 700
#define V3B 700

__device__ __forceinline__ unsigned long long ffma2(unsigned long long a,
                                                    unsigned long long b,
                                                    unsigned long long c) {
    unsigned long long d;
    asm("fma.rn.f32x2 %0, %1, %2, %3;" : "=l"(d) : "l"(a), "l"(b), "l"(c));
    return d;
}
__device__ __forceinline__ float fast_ex2(float x) {
    float y; asm("ex2.approx.ftz.f32 %0, %1;" : "=f"(y) : "f"(x)); return y;
}
__device__ __forceinline__ float fast_rcp(float x) {
    float y; asm("rcp.approx.ftz.f32 %0, %1;" : "=f"(y) : "f"(x)); return y;
}
__device__ __forceinline__ float sigm(float x) {
    return fast_rcp(1.0f + fast_ex2(-1.4426950408889634f * x));
}
__device__ __forceinline__ float tanh_acc(float x) {
    float r = fast_rcp(1.0f + fast_ex2(-2.8853900817779268f * x));
    return r + r - 1.0f;
}

// Accumulate 4 gate rows (j, j+50, j+100, j+150) over kq = ks, ks+4, ... < KQ
// for all NB batches. Result: s[g][b] = this thread's K-slice partial sum.
template<int KQ, int VS>
__device__ __forceinline__ void gate_accum(const float* __restrict__ shw,
                                           const float* __restrict__ shv,
                                           int j, int ks, float s[4][NB]) {
    unsigned long long acc[4][NB];
#pragma unroll
    for (int g = 0; g < 4; g++)
#pragma unroll
        for (int b = 0; b < NB; b++) acc[g][b] = 0ull;

#pragma unroll 2
    for (int kq = ks; kq < KQ; kq += 4) {
        const ulonglong2* wq =
            reinterpret_cast<const ulonglong2*>(shw + kq * WSTR);
        ulonglong2 w0 = wq[j];
        ulonglong2 w1 = wq[j + HID];
        ulonglong2 w2 = wq[j + 2 * HID];
        ulonglong2 w3 = wq[j + 3 * HID];
#pragma unroll
        for (int b = 0; b < NB; b++) {
            ulonglong2 v = *reinterpret_cast<const ulonglong2*>(
                shv + b * VS + kq * 4);
            acc[0][b] = ffma2(w0.x, v.x, acc[0][b]);
            acc[0][b] = ffma2(w0.y, v.y, acc[0][b]);
            acc[1][b] = ffma2(w1.x, v.x, acc[1][b]);
            acc[1][b] = ffma2(w1.y, v.y, acc[1][b]);
            acc[2][b] = ffma2(w2.x, v.x, acc[2][b]);
            acc[2][b] = ffma2(w2.y, v.y, acc[2][b]);
            acc[3][b] = ffma2(w3.x, v.x, acc[3][b]);
            acc[3][b] = ffma2(w3.y, v.y, acc[3][b]);
        }
    }
#pragma unroll
    for (int g = 0; g < 4; g++)
#pragma unroll
        for (int b = 0; b < NB; b++) {
            float lo, hi;
            asm("mov.b64 {%0, %1}, %2;" : "=f"(lo), "=f"(hi) : "l"(acc[g][b]));
            s[g][b] = lo + hi;
        }
}

__device__ __forceinline__ void reduce4(float s[4][NB], unsigned mask) {
#pragma unroll
    for (int g = 0; g < 4; g++)
#pragma unroll
        for (int b = 0; b < NB; b++) {
            s[g][b] += __shfl_xor_sync(mask, s[g][b], 1);
            s[g][b] += __shfl_xor_sync(mask, s[g][b], 2);
        }
}

__device__ __forceinline__ void update_one(const float s[4][NB], int b,
                                           const float* bz, float& c,
                                           float* sh, int d1, int d2,
                                           bool has2) {
    float iv = sigm(s[0][b] + bz[0]);
    float fv = sigm(s[1][b] + bz[1]);
    float gv = tanh_acc(s[2][b] + bz[2]);
    float ov = sigm(s[3][b] + bz[3]);
    c = fv * c + iv * gv;
    float h = ov * tanh_acc(c);
    sh[d1] = h;
    if (has2) sh[d2] = h;
}

__global__ void __launch_bounds__(NTHREADS, 1)
lstm3_fused_kernel(const float* __restrict__ x,
                   const float* __restrict__ Wih1, const float* __restrict__ Whh1,
                   const float* __restrict__ bih1, const float* __restrict__ bhh1,
                   const float* __restrict__ Wih2, const float* __restrict__ Whh2,
                   const float* __restrict__ bih2, const float* __restrict__ bhh2,
                   const float* __restrict__ Wih3, const float* __restrict__ Whh3,
                   const float* __restrict__ bih3, const float* __restrict__ bhh3,
                   const float* __restrict__ fcW, const float* __restrict__ fcb,
                   float* __restrict__ out) {
    extern __shared__ float sh[];
    const int tid = threadIdx.x;
    const int bid = blockIdx.x;

    int b0, cnt;
    if (bid < 136) { b0 = bid * 7;               cnt = 7; }
    else           { b0 = 952 + (bid - 136) * 6; cnt = 6; }

    // zero v buffers (both parities)
    for (int i = V1_OFF + tid; i < SH_FLOATS; i += NTHREADS) sh[i] = 0.0f;

    // stage weights: [kq][gate][k&3], kq-stride WSTR
    for (int idx = tid; idx < 200 * 56; idx += NTHREADS) {
        int g = idx / 56, k = idx - g * 56;
        float v;
        if (k < IN_DIM)       v = Wih1[g * IN_DIM + k];
        else if (k == IN_DIM) v = 0.0f;
        else                  v = Whh1[g * HID + (k - 6)];
        sh[W1_OFF + (k >> 2) * WSTR + g * 4 + (k & 3)] = v;
    }
    for (int idx = tid; idx < 200 * 100; idx += NTHREADS) {
        int g = idx / 100, k = idx - g * 100;
        float v = (k < HID) ? Wih2[g * HID + k] : Whh2[g * HID + (k - HID)];
        sh[W2_OFF + (k >> 2) * WSTR + g * 4 + (k & 3)] = v;
    }
    for (int idx = tid; idx < 200 * 100; idx += NTHREADS) {
        int g = idx / 100, k = idx - g * 100;
        float v = (k < HID) ? Wih3[g * HID + k] : Whh3[g * HID + (k - HID)];
        sh[W3_OFF + (k >> 2) * WSTR + g * 4 + (k & 3)] = v;
    }
    for (int idx = tid; idx < 600; idx += NTHREADS) {
        int l = idx / 200, g = idx - l * 200;
        const float* bi = (l == 0) ? bih1 : (l == 1) ? bih2 : bih3;
        const float* bh = (l == 0) ? bhh1 : (l == 1) ? bhh2 : bhh3;
        sh[BS_OFF + idx] = bi[g] + bh[g];
    }
    // x(t=0) into v1 buf0
    if (tid < NB * IN_DIM) {
        int b = tid / IN_DIM, d = tid - b * IN_DIM;
        if (b < cnt)
            sh[V1_OFF + b * 56 + d] = x[(size_t)(b0 + b) * T_STEPS * IN_DIM + d];
    }
    __syncthreads();

    const bool gate = (tid < 200);
    const int j  = tid >> 2;        // 0..49
    const int ks = tid & 3;         // 0..3
    const unsigned mask = (tid < 192) ? 0xFFFFFFFFu : 0x000000FFu;

    // per-thread bias regs (4 gates x 3 layers)
    float bz1[4], bz2[4], bz3[4];
    if (gate) {
#pragma unroll
        for (int g = 0; g < 4; g++) {
            bz1[g] = sh[BS_OFF +       g * HID + j];
            bz2[g] = sh[BS_OFF + 200 + g * HID + j];
            bz3[g] = sh[BS_OFF + 400 + g * HID + j];
        }
    }
    // cell states live in registers: batches {ks, ks+4}
    float c1[2] = {0.f, 0.f}, c2[2] = {0.f, 0.f}, c3[2] = {0.f, 0.f};
    const int ob0 = ks, ob1 = ks + 4;
    const bool two = (ks < 3);

    // prefetch slot for spare threads
    int pb = 0, pd = 0; bool pth = false;
    if (tid >= 200 && tid < 200 + NB * IN_DIM) {
        int i = tid - 200;
        pb = i / IN_DIM; pd = i - pb * IN_DIM;
        pth = (pb < cnt);
    }

    for (int t = 0; t < T_STEPS; t++) {
        const int p = t & 1, q = p ^ 1;
        float xv = 0.0f;
        bool pv = pth && (t + 1 < T_STEPS);

        // ---- layer 1 ----
        if (gate) {
            float s[4][NB];
            gate_accum<14, 56>(sh + W1_OFF, sh + V1_OFF + p * V1B, j, ks, s);
            reduce4(s, mask);
            update_one(s, ob0, bz1, c1[0], sh,
                       V1_OFF + q * V1B + ob0 * 56 + 6 + j,
                       V2_OFF + p * V2B + ob0 * 100 + j, true);
            if (two)
                update_one(s, ob1, bz1, c1[1], sh,
                           V1_OFF + q * V1B + ob1 * 56 + 6 + j,
                           V2_OFF + p * V2B + ob1 * 100 + j, true);
        } else if (pv) {
            xv = x[(size_t)(b0 + pb) * T_STEPS * IN_DIM + (t + 1) * IN_DIM + pd];
        }
        __syncthreads();

        // ---- layer 2 ----
        if (gate) {
            float s[4][NB];
            gate_accum<25, 100>(sh + W2_OFF, sh + V2_OFF + p * V2B, j, ks, s);
            reduce4(s, mask);
            update_one(s, ob0, bz2, c2[0], sh,
                       V2_OFF + q * V2B + ob0 * 100 + HID + j,
                       V3_OFF + p * V3B + ob0 * 100 + j, true);
            if (two)
                update_one(s, ob1, bz2, c2[1], sh,
                           V2_OFF + q * V2B + ob1 * 100 + HID + j,
                           V3_OFF + p * V3B + ob1 * 100 + j, true);
        } else if (pv) {
            sh[V1_OFF + q * V1B + pb * 56 + pd] = xv;   // commit x(t+1)
        }
        __syncthreads();

        // ---- layer 3 ----
        if (gate) {
            float s[4][NB];
            gate_accum<25, 100>(sh + W3_OFF, sh + V3_OFF + p * V3B, j, ks, s);
            reduce4(s, mask);
            update_one(s, ob0, bz3, c3[0], sh,
                       V3_OFF + q * V3B + ob0 * 100 + HID + j, 0, false);
            if (two)
                update_one(s, ob1, bz3, c3[1], sh,
                           V3_OFF + q * V3B + ob1 * 100 + HID + j, 0, false);
        }
        __syncthreads();
    }

    // FC: final h3 sits in v3 buf0 (last write parity q=0)
    if (tid < cnt) {
        float a = fcb[0];
#pragma unroll
        for (int jj = 0; jj < HID; jj++)
            a += fcW[jj] * sh[V3_OFF + tid * 100 + HID + jj];
        out[b0 + tid] = a;
    }
}

extern "C" void kernel_launch(void* const* d_in, const int* in_sizes, int n_in,
                              void* d_out, int out_size) {
    const float* x    = (const float*)d_in[0];
    const float* Wih1 = (const float*)d_in[1];
    const float* Whh1 = (const float*)d_in[2];
    const float* bih1 = (const float*)d_in[3];
    const float* bhh1 = (const float*)d_in[4];
    const float* Wih2 = (const float*)d_in[5];
    const float* Whh2 = (const float*)d_in[6];
    const float* bih2 = (const float*)d_in[7];
    const float* bhh2 = (const float*)d_in[8];
    const float* Wih3 = (const float*)d_in[9];
    const float* Whh3 = (const float*)d_in[10];
    const float* bih3 = (const float*)d_in[11];
    const float* bhh3 = (const float*)d_in[12];
    const float* fcW  = (const float*)d_in[13];
    const float* fcb  = (const float*)d_in[14];

    size_t shbytes = (size_t)SH_FLOATS * sizeof(float);
    cudaFuncSetAttribute(lstm3_fused_kernel,
                         cudaFuncAttributeMaxDynamicSharedMemorySize,
                         (int)shbytes);
    lstm3_fused_kernel<<<GRID, NTHREADS, shbytes>>>(
        x, Wih1, Whh1, bih1, bhh1, Wih2, Whh2, bih2, bhh2,
        Wih3, Whh3, bih3, bhh3, fcW, fcb, (float*)d_out);
}

// round 3
// speedup vs baseline: 1.0012x; 1.0012x over previous
#include <cuda_runtime.h>

// 3-layer LSTM (IN=5, H=50) + FC(50->1), B=1024, T=512.
// Fused persistent kernel, v2: j-ownership + K-split.
//  - thread (j, ks): accumulates gates {j, j+50, j+100, j+150} over its K/4
//    slice (kq = ks, ks+4, ...) for all 7 batch elems; 2-round shfl.bfly
//    combines the 4 K-partials; the 4 owning threads then apply activations
//    and the c/h update in-registers (c never touches smem).
//  - v vectors double-buffered on t-parity: 3 barriers/step total.
//  - weights in smem, [kq][gate][4k] with kq-stride 808 words (=8 mod 32
//    banks) so warp LDS.128 of w and v are conflict-free.

#define T_STEPS   512
#define IN_DIM    5
#define HID       50
#define NB        7
#define NTHREADS  256
#define GRID      148
#define WSTR      808          // floats per kq block (200 gates * 4 + 8 pad)

// smem offsets (floats)
enum {
    W1_OFF = 0,                // 14 kq * 808
    W2_OFF = 11312,            // 25 kq * 808
    W3_OFF = 31512,
    BS_OFF = 51712,            // 3 * 200 combined biases
    V1_OFF = 52312,            // 2 bufs * 7 * 56
    V2_OFF = 53096,            // 2 bufs * 7 * 100
    V3_OFF = 54496,
    SH_FLOATS = 55896          // 223584 bytes
};
#define V1B 392
#define V2B 700
#define V3B 700

__device__ __forceinline__ unsigned long long ffma2(unsigned long long a,
                                                    unsigned long long b,
                                                    unsigned long long c) {
    unsigned long long d;
    asm("fma.rn.f32x2 %0, %1, %2, %3;" : "=l"(d) : "l"(a), "l"(b), "l"(c));
    return d;
}
__device__ __forceinline__ float fast_ex2(float x) {
    float y; asm("ex2.approx.ftz.f32 %0, %1;" : "=f"(y) : "f"(x)); return y;
}
__device__ __forceinline__ float fast_rcp(float x) {
    float y; asm("rcp.approx.ftz.f32 %0, %1;" : "=f"(y) : "f"(x)); return y;
}
__device__ __forceinline__ float sigm(float x) {
    return fast_rcp(1.0f + fast_ex2(-1.4426950408889634f * x));
}
__device__ __forceinline__ float tanh_acc(float x) {
    float r = fast_rcp(1.0f + fast_ex2(-2.8853900817779268f * x));
    return r + r - 1.0f;
}

// Accumulate 4 gate rows (j, j+50, j+100, j+150) over kq = ks, ks+4, ... < KQ
// for all NB batches. Result: s[g][b] = this thread's K-slice partial sum.
template<int KQ, int VS>
__device__ __forceinline__ void gate_accum(const float* __restrict__ shw,
                                           const float* __restrict__ shv,
                                           int j, int ks, float s[4][NB]) {
    unsigned long long acc[4][NB];
#pragma unroll
    for (int g = 0; g < 4; g++)
#pragma unroll
        for (int b = 0; b < NB; b++) acc[g][b] = 0ull;

#pragma unroll 2
    for (int kq = ks; kq < KQ; kq += 4) {
        const ulonglong2* wq =
            reinterpret_cast<const ulonglong2*>(shw + kq * WSTR);
        ulonglong2 w0 = wq[j];
        ulonglong2 w1 = wq[j + HID];
        ulonglong2 w2 = wq[j + 2 * HID];
        ulonglong2 w3 = wq[j + 3 * HID];
#pragma unroll
        for (int b = 0; b < NB; b++) {
            ulonglong2 v = *reinterpret_cast<const ulonglong2*>(
                shv + b * VS + kq * 4);
            acc[0][b] = ffma2(w0.x, v.x, acc[0][b]);
            acc[0][b] = ffma2(w0.y, v.y, acc[0][b]);
            acc[1][b] = ffma2(w1.x, v.x, acc[1][b]);
            acc[1][b] = ffma2(w1.y, v.y, acc[1][b]);
            acc[2][b] = ffma2(w2.x, v.x, acc[2][b]);
            acc[2][b] = ffma2(w2.y, v.y, acc[2][b]);
            acc[3][b] = ffma2(w3.x, v.x, acc[3][b]);
            acc[3][b] = ffma2(w3.y, v.y, acc[3][b]);
        }
    }
#pragma unroll
    for (int g = 0; g < 4; g++)
#pragma unroll
        for (int b = 0; b < NB; b++) {
            float lo, hi;
            asm("mov.b64 {%0, %1}, %2;" : "=f"(lo), "=f"(hi) : "l"(acc[g][b]));
            s[g][b] = lo + hi;
        }
}

__device__ __forceinline__ void reduce4(float s[4][NB], unsigned mask) {
#pragma unroll
    for (int g = 0; g < 4; g++)
#pragma unroll
        for (int b = 0; b < NB; b++) {
            s[g][b] += __shfl_xor_sync(mask, s[g][b], 1);
            s[g][b] += __shfl_xor_sync(mask, s[g][b], 2);
        }
}

__device__ __forceinline__ void update_one(const float s[4][NB], int b,
                                           const float* bz, float& c,
                                           float* sh, int d1, int d2,
                                           bool has2) {
    float iv = sigm(s[0][b] + bz[0]);
    float fv = sigm(s[1][b] + bz[1]);
    float gv = tanh_acc(s[2][b] + bz[2]);
    float ov = sigm(s[3][b] + bz[3]);
    c = fv * c + iv * gv;
    float h = ov * tanh_acc(c);
    sh[d1] = h;
    if (has2) sh[d2] = h;
}

__global__ void __launch_bounds__(NTHREADS, 1)
lstm3_fused_kernel(const float* __restrict__ x,
                   const float* __restrict__ Wih1, const float* __restrict__ Whh1,
                   const float* __restrict__ bih1, const float* __restrict__ bhh1,
                   const float* __restrict__ Wih2, const float* __restrict__ Whh2,
                   const float* __restrict__ bih2, const float* __restrict__ bhh2,
                   const float* __restrict__ Wih3, const float* __restrict__ Whh3,
                   const float* __restrict__ bih3, const float* __restrict__ bhh3,
                   const float* __restrict__ fcW, const float* __restrict__ fcb,
                   float* __restrict__ out) {
    extern __shared__ float sh[];
    const int tid = threadIdx.x;
    const int bid = blockIdx.x;

    int b0, cnt;
    if (bid < 136) { b0 = bid * 7;               cnt = 7; }
    else           { b0 = 952 + (bid - 136) * 6; cnt = 6; }

    // zero v buffers (both parities)
    for (int i = V1_OFF + tid; i < SH_FLOATS; i += NTHREADS) sh[i] = 0.0f;

    // stage weights: [kq][gate][k&3], kq-stride WSTR
    for (int idx = tid; idx < 200 * 56; idx += NTHREADS) {
        int g = idx / 56, k = idx - g * 56;
        float v;
        if (k < IN_DIM)       v = Wih1[g * IN_DIM + k];
        else if (k == IN_DIM) v = 0.0f;
        else                  v = Whh1[g * HID + (k - 6)];
        sh[W1_OFF + (k >> 2) * WSTR + g * 4 + (k & 3)] = v;
    }
    for (int idx = tid; idx < 200 * 100; idx += NTHREADS) {
        int g = idx / 100, k = idx - g * 100;
        float v = (k < HID) ? Wih2[g * HID + k] : Whh2[g * HID + (k - HID)];
        sh[W2_OFF + (k >> 2) * WSTR + g * 4 + (k & 3)] = v;
    }
    for (int idx = tid; idx < 200 * 100; idx += NTHREADS) {
        int g = idx / 100, k = idx - g * 100;
        float v = (k < HID) ? Wih3[g * HID + k] : Whh3[g * HID + (k - HID)];
        sh[W3_OFF + (k >> 2) * WSTR + g * 4 + (k & 3)] = v;
    }
    for (int idx = tid; idx < 600; idx += NTHREADS) {
        int l = idx / 200, g = idx - l * 200;
        const float* bi = (l == 0) ? bih1 : (l == 1) ? bih2 : bih3;
        const float* bh = (l == 0) ? bhh1 : (l == 1) ? bhh2 : bhh3;
        sh[BS_OFF + idx] = bi[g] + bh[g];
    }
    // x(t=0) into v1 buf0
    if (tid < NB * IN_DIM) {
        int b = tid / IN_DIM, d = tid - b * IN_DIM;
        if (b < cnt)
            sh[V1_OFF + b * 56 + d] = x[(size_t)(b0 + b) * T_STEPS * IN_DIM + d];
    }
    __syncthreads();

    const bool gate = (tid < 200);
    const int j  = tid >> 2;        // 0..49
    const int ks = tid & 3;         // 0..3
    const unsigned mask = (tid < 192) ? 0xFFFFFFFFu : 0x000000FFu;

    // per-thread bias regs (4 gates x 3 layers)
    float bz1[4], bz2[4], bz3[4];
    if (gate) {
#pragma unroll
        for (int g = 0; g < 4; g++) {
            bz1[g] = sh[BS_OFF +       g * HID + j];
            bz2[g] = sh[BS_OFF + 200 + g * HID + j];
            bz3[g] = sh[BS_OFF + 400 + g * HID + j];
        }
    }
    // cell states live in registers: batches {ks, ks+4}
    float c1[2] = {0.f, 0.f}, c2[2] = {0.f, 0.f}, c3[2] = {0.f, 0.f};
    const int ob0 = ks, ob1 = ks + 4;
    const bool two = (ks < 3);

    // prefetch slot for spare threads
    int pb = 0, pd = 0; bool pth = false;
    if (tid >= 200 && tid < 200 + NB * IN_DIM) {
        int i = tid - 200;
        pb = i / IN_DIM; pd = i - pb * IN_DIM;
        pth = (pb < cnt);
    }

    for (int t = 0; t < T_STEPS; t++) {
        const int p = t & 1, q = p ^ 1;
        float xv = 0.0f;
        bool pv = pth && (t + 1 < T_STEPS);

        // ---- layer 1 ----
        if (gate) {
            float s[4][NB];
            gate_accum<14, 56>(sh + W1_OFF, sh + V1_OFF + p * V1B, j, ks, s);
            reduce4(s, mask);
            update_one(s, ob0, bz1, c1[0], sh,
                       V1_OFF + q * V1B + ob0 * 56 + 6 + j,
                       V2_OFF + p * V2B + ob0 * 100 + j, true);
            if (two)
                update_one(s, ob1, bz1, c1[1], sh,
                           V1_OFF + q * V1B + ob1 * 56 + 6 + j,
                           V2_OFF + p * V2B + ob1 * 100 + j, true);
        } else if (pv) {
            xv = x[(size_t)(b0 + pb) * T_STEPS * IN_DIM + (t + 1) * IN_DIM + pd];
        }
        __syncthreads();

        // ---- layer 2 ----
        if (gate) {
            float s[4][NB];
            gate_accum<25, 100>(sh + W2_OFF, sh + V2_OFF + p * V2B, j, ks, s);
            reduce4(s, mask);
            update_one(s, ob0, bz2, c2[0], sh,
                       V2_OFF + q * V2B + ob0 * 100 + HID + j,
                       V3_OFF + p * V3B + ob0 * 100 + j, true);
            if (two)
                update_one(s, ob1, bz2, c2[1], sh,
                           V2_OFF + q * V2B + ob1 * 100 + HID + j,
                           V3_OFF + p * V3B + ob1 * 100 + j, true);
        } else if (pv) {
            sh[V1_OFF + q * V1B + pb * 56 + pd] = xv;   // commit x(t+1)
        }
        __syncthreads();

        // ---- layer 3 ----
        if (gate) {
            float s[4][NB];
            gate_accum<25, 100>(sh + W3_OFF, sh + V3_OFF + p * V3B, j, ks, s);
            reduce4(s, mask);
            update_one(s, ob0, bz3, c3[0], sh,
                       V3_OFF + q * V3B + ob0 * 100 + HID + j, 0, false);
            if (two)
                update_one(s, ob1, bz3, c3[1], sh,
                           V3_OFF + q * V3B + ob1 * 100 + HID + j, 0, false);
        }
        __syncthreads();
    }

    // FC: final h3 sits in v3 buf0 (last write parity q=0)
    if (tid < cnt) {
        float a = fcb[0];
#pragma unroll
        for (int jj = 0; jj < HID; jj++)
            a += fcW[jj] * sh[V3_OFF + tid * 100 + HID + jj];
        out[b0 + tid] = a;
    }
}

extern "C" void kernel_launch(void* const* d_in, const int* in_sizes, int n_in,
                              void* d_out, int out_size) {
    const float* x    = (const float*)d_in[0];
    const float* Wih1 = (const float*)d_in[1];
    const float* Whh1 = (const float*)d_in[2];
    const float* bih1 = (const float*)d_in[3];
    const float* bhh1 = (const float*)d_in[4];
    const float* Wih2 = (const float*)d_in[5];
    const float* Whh2 = (const float*)d_in[6];
    const float* bih2 = (const float*)d_in[7];
    const float* bhh2 = (const float*)d_in[8];
    const float* Wih3 = (const float*)d_in[9];
    const float* Whh3 = (const float*)d_in[10];
    const float* bih3 = (const float*)d_in[11];
    const float* bhh3 = (const float*)d_in[12];
    const float* fcW  = (const float*)d_in[13];
    const float* fcb  = (const float*)d_in[14];

    size_t shbytes = (size_t)SH_FLOATS * sizeof(float);
    cudaFuncSetAttribute(lstm3_fused_kernel,
                         cudaFuncAttributeMaxDynamicSharedMemorySize,
                         (int)shbytes);
    lstm3_fused_kernel<<<GRID, NTHREADS, shbytes>>>(
        x, Wih1, Whh1, bih1, bhh1, Wih2, Whh2, bih2, bhh2,
        Wih3, Whh3, bih3, bhh3, fcW, fcb, (float*)d_out);
}